// round 12
// baseline (speedup 1.0000x reference)
#include <cuda_runtime.h>
#include <cstddef>
#include <cstdint>

#define R_DIM 64
#define I_DIM 256
#define O_DIM 256
#define TILE_M 128

// Scratch: per-chunk partial sums of W over i.
__device__ float g_wpart[8][R_DIM * O_DIM];

// ---------------------------------------------------------------------------
// W partials: g_wpart[chunk][r][o] = sum_{i in chunk} W[r][i][o]
// ---------------------------------------------------------------------------
__global__ void wsum_part_kernel(const float* __restrict__ W) {
    const int r = blockIdx.x, chunk = blockIdx.y, o = threadIdx.x;
    const float* p = W + ((size_t)r * I_DIM + chunk * 32) * O_DIM + o;
    float s = 0.0f;
#pragma unroll
    for (int i = 0; i < 32; ++i) s += p[(size_t)i * O_DIM];
    g_wpart[chunk][r * O_DIM + o] = s;
}

// ---------------------------------------------------------------------------
// Helpers
// ---------------------------------------------------------------------------
// Canonical (CUTLASS-style) tf32 round: b32 destination register.
__device__ __forceinline__ uint32_t cvt_tf32(float v) {
    uint32_t r;
    asm("cvt.rna.tf32.f32 %0, %1;" : "=r"(r) : "f"(v));
    return r;
}
__device__ __forceinline__ float frcp(float v) {
    float r; asm("rcp.approx.f32 %0, %1;" : "=f"(r) : "f"(v)); return r;
}
// m16n8k8 tf32 MMA, D += A*B (C aliased to D).
__device__ __forceinline__ void mma8(float* d, const uint32_t* a,
                                     uint32_t b0, uint32_t b1) {
    asm volatile(
        "mma.sync.aligned.m16n8k8.row.col.f32.tf32.tf32.f32 "
        "{%0,%1,%2,%3},{%4,%5,%6,%7},{%8,%9},{%0,%1,%2,%3};"
        : "+f"(d[0]), "+f"(d[1]), "+f"(d[2]), "+f"(d[3])
        : "r"(a[0]), "r"(a[1]), "r"(a[2]), "r"(a[3]), "r"(b0), "r"(b1));
}

// Shared layout (floats): Bh[64*264], Bl[64*264], A[128*68]
#define BSTR 264
#define ASTR 68
#define OFF_BH 0
#define OFF_BL (64 * BSTR)
#define OFF_A  (2 * 64 * BSTR)
#define SMEM_DYN ((2 * 64 * BSTR + TILE_M * ASTR) * 4)

// ---------------------------------------------------------------------------
// Main: out[e][o] = x_sum[e] * sum_r (1/cs[e][r]) * Wsum[r][o]
// via mma.sync tf32, 3-product precision split, persistent CTAs.
// Tile 128x256, K=64. Warp w owns rows 16w..16w+15.
// ---------------------------------------------------------------------------
__global__ void __launch_bounds__(256, 1)
rgcn_mma_kernel(const float* __restrict__ x, const float* __restrict__ cs,
                float* __restrict__ out, int E, int ntiles) {
    extern __shared__ float sm[];
    float* Bh = sm + OFF_BH;
    float* Bl = sm + OFF_BL;
    float* Ash = sm + OFF_A;
    __shared__ float s_xsum[TILE_M];

    const int t = threadIdx.x, wid = t >> 5, lane = t & 31;
    const int g = lane >> 2, tig = lane & 3;

    // ---- Build B hi/lo from W partials (once per CTA) ----
    for (int idx = t; idx < R_DIM * O_DIM; idx += 256) {
        const int r = idx >> 8, o = idx & 255;
        float v = 0.0f;
#pragma unroll
        for (int c = 0; c < 8; ++c) v += g_wpart[c][idx];
        uint32_t hb = cvt_tf32(v);
        float hf = __uint_as_float(hb);
        Bh[r * BSTR + o] = hf;
        Bl[r * BSTR + o] = __uint_as_float(cvt_tf32(v - hf));
    }
    __syncthreads();

    const int r0 = 16 * wid + g;  // this lane's first output row within tile

    for (int tile = blockIdx.x; tile < ntiles; tile += gridDim.x) {
        const int ebase = tile * TILE_M;

        // ---- Build A (fp32 reciprocals of cs) into shared ----
        {
            const int el0 = t >> 6, k = t & 63;
#pragma unroll 8
            for (int q = 0; q < 32; ++q) {
                const int el = el0 + q * 4;
                const int e = ebase + el;
                float v = 0.0f;
                if (e < E) v = frcp(cs[(size_t)e * R_DIM + k]);
                Ash[el * ASTR + k] = v;
            }
        }
        __syncthreads();

        // ---- Load A fragments (hi/lo) into registers ----
        // m16n8k8 A layout: a0=(g,tig) a1=(g+8,tig) a2=(g,tig+4) a3=(g+8,tig+4)
        uint32_t ah[8][4], al[8][4];
#pragma unroll
        for (int ks = 0; ks < 8; ++ks) {
            const int c0 = ks * 8 + tig;
            float v0 = Ash[r0 * ASTR + c0];
            float v1 = Ash[(r0 + 8) * ASTR + c0];
            float v2 = Ash[r0 * ASTR + c0 + 4];
            float v3 = Ash[(r0 + 8) * ASTR + c0 + 4];
            ah[ks][0] = cvt_tf32(v0);
            ah[ks][1] = cvt_tf32(v1);
            ah[ks][2] = cvt_tf32(v2);
            ah[ks][3] = cvt_tf32(v3);
            al[ks][0] = cvt_tf32(v0 - __uint_as_float(ah[ks][0]));
            al[ks][1] = cvt_tf32(v1 - __uint_as_float(ah[ks][1]));
            al[ks][2] = cvt_tf32(v2 - __uint_as_float(ah[ks][2]));
            al[ks][3] = cvt_tf32(v3 - __uint_as_float(ah[ks][3]));
        }

        // ---- x row sums: warp wid owns rows 16*wid .. 16*wid+15 ----
#pragma unroll 1
        for (int rr = 0; rr < 16; ++rr) {
            const int row = wid * 16 + rr;
            const int e = ebase + row;
            float s = 0.0f;
            if (e < E) {
                const float4* xp = (const float4*)(x + (size_t)e * I_DIM);
                float4 a = xp[lane], b = xp[lane + 32];
                s = ((a.x + a.y) + (a.z + a.w)) + ((b.x + b.y) + (b.z + b.w));
            }
#pragma unroll
            for (int off = 16; off; off >>= 1)
                s += __shfl_xor_sync(0xffffffffu, s, off);
            if (lane == 0) s_xsum[row] = s;
        }
        __syncwarp();
        const float xs0 = s_xsum[r0];
        const float xs1 = s_xsum[r0 + 8];

        const int e0 = ebase + r0, e1 = e0 + 8;

        // ---- Four N-quarter passes (64 cols each) of MMAs + direct store ----
#pragma unroll
        for (int nq = 0; nq < 4; ++nq) {
            float acc[8][4];
#pragma unroll
            for (int nt = 0; nt < 8; ++nt) {
                acc[nt][0] = 0.f; acc[nt][1] = 0.f;
                acc[nt][2] = 0.f; acc[nt][3] = 0.f;
            }
#pragma unroll
            for (int ks = 0; ks < 8; ++ks) {
                // B layout: b0 = B[k=tig][n=g], b1 = B[k=tig+4][n=g]
                const float* ph0 = &Bh[(ks * 8 + tig) * BSTR + nq * 64 + g];
                const float* ph1 = &Bh[(ks * 8 + tig + 4) * BSTR + nq * 64 + g];
                const float* pl0 = &Bl[(ks * 8 + tig) * BSTR + nq * 64 + g];
                const float* pl1 = &Bl[(ks * 8 + tig + 4) * BSTR + nq * 64 + g];
#pragma unroll
                for (int nt = 0; nt < 8; ++nt) {
                    uint32_t bh0 = __float_as_uint(ph0[nt * 8]);
                    uint32_t bh1 = __float_as_uint(ph1[nt * 8]);
                    uint32_t bl0 = __float_as_uint(pl0[nt * 8]);
                    uint32_t bl1 = __float_as_uint(pl1[nt * 8]);
                    mma8(acc[nt], ah[ks], bh0, bh1);
                    mma8(acc[nt], al[ks], bh0, bh1);
                    mma8(acc[nt], ah[ks], bl0, bl1);
                }
            }
            // store: c0/c1 -> row r0, c2/c3 -> row r0+8; cols 2*tig,2*tig+1
#pragma unroll
            for (int nt = 0; nt < 8; ++nt) {
                const int col = nq * 64 + nt * 8 + 2 * tig;
                if (e0 < E) {
                    float2 v = make_float2(acc[nt][0] * xs0, acc[nt][1] * xs0);
                    *(float2*)&out[(size_t)e0 * O_DIM + col] = v;
                }
                if (e1 < E) {
                    float2 v = make_float2(acc[nt][2] * xs1, acc[nt][3] * xs1);
                    *(float2*)&out[(size_t)e1 * O_DIM + col] = v;
                }
            }
        }
        __syncthreads();  // all frag loads done before next tile overwrites Ash
    }
}

// ---------------------------------------------------------------------------
// Launch. Inputs (metadata order): x (E*I f32), cs (E*R f32), W (R*I*O f32),
// edge_index (dead). Output: (E, O) f32.
// ---------------------------------------------------------------------------
extern "C" void kernel_launch(void* const* d_in, const int* in_sizes, int n_in,
                              void* d_out, int out_size) {
    const float* x  = (const float*)d_in[0];
    const float* cs = (const float*)d_in[1];
    const float* W  = (const float*)d_in[2];
    float* out = (float*)d_out;

    const int E = in_sizes[1] / R_DIM;
    const int ntiles = (E + TILE_M - 1) / TILE_M;

    dim3 wgrid(R_DIM, 8);
    wsum_part_kernel<<<wgrid, O_DIM>>>(W);

    cudaFuncSetAttribute(rgcn_mma_kernel,
                         cudaFuncAttributeMaxDynamicSharedMemorySize, SMEM_DYN);
    int grid = 148;
    if (grid > ntiles) grid = ntiles;
    rgcn_mma_kernel<<<grid, 256, SMEM_DYN>>>(x, cs, out, E, ntiles);
}

// round 13
// speedup vs baseline: 1.2005x; 1.2005x over previous
#include <cuda_runtime.h>
#include <cstddef>
#include <cstdint>

#define R_DIM 64
#define I_DIM 256
#define O_DIM 256
#define TILE_M 128
#define NTHREADS 512

// Scratch: per-chunk partial sums of W over i.
__device__ float g_wpart[8][R_DIM * O_DIM];

// ---------------------------------------------------------------------------
// W partials: g_wpart[chunk][r][o] = sum_{i in chunk} W[r][i][o]
// ---------------------------------------------------------------------------
__global__ void wsum_part_kernel(const float* __restrict__ W) {
    const int r = blockIdx.x, chunk = blockIdx.y, o = threadIdx.x;
    const float* p = W + ((size_t)r * I_DIM + chunk * 32) * O_DIM + o;
    float s = 0.0f;
#pragma unroll
    for (int i = 0; i < 32; ++i) s += p[(size_t)i * O_DIM];
    g_wpart[chunk][r * O_DIM + o] = s;
}

// ---------------------------------------------------------------------------
// Helpers
// ---------------------------------------------------------------------------
__device__ __forceinline__ uint32_t cvt_tf32(float v) {
    uint32_t r;
    asm("cvt.rna.tf32.f32 %0, %1;" : "=r"(r) : "f"(v));
    return r;
}
__device__ __forceinline__ float frcp(float v) {
    float r; asm("rcp.approx.f32 %0, %1;" : "=f"(r) : "f"(v)); return r;
}
// m16n8k8 tf32 MMA, D += A*B (C aliased to D).
__device__ __forceinline__ void mma8(float* d, const uint32_t* a,
                                     uint32_t b0, uint32_t b1) {
    asm volatile(
        "mma.sync.aligned.m16n8k8.row.col.f32.tf32.tf32.f32 "
        "{%0,%1,%2,%3},{%4,%5,%6,%7},{%8,%9},{%0,%1,%2,%3};"
        : "+f"(d[0]), "+f"(d[1]), "+f"(d[2]), "+f"(d[3])
        : "r"(a[0]), "r"(a[1]), "r"(a[2]), "r"(a[3]), "r"(b0), "r"(b1));
}

// Shared layout (floats).
// Bp (permuted): Bp[Q][k][g*8+nt], Q=0..3 (64-col quarters), k=0..63,
//   stride 68 for bank spread. Frag load = two LDS.128 per row.
// A hi/lo: [128][68] each, pre-split tf32 hi + fp32 residual-lo.
#define BROW 68
#define ASTR 68
#define OFF_BPH 0
#define OFF_BPL (4 * 64 * BROW)
#define OFF_AH  (2 * 4 * 64 * BROW)
#define OFF_AL  (OFF_AH + TILE_M * ASTR)
#define SMEM_DYN ((OFF_AL + TILE_M * ASTR) * 4)

// ---------------------------------------------------------------------------
// Main: out[e][o] = x_sum[e] * sum_r (1/cs[e][r]) * Wsum[r][o]
// mma.sync tf32, 3-product split, persistent CTAs, 512 threads.
// Warps 0-7: cols 0-127. Warps 8-15: cols 128-255. All share rows 0-127.
// ---------------------------------------------------------------------------
__global__ void __launch_bounds__(NTHREADS, 1)
rgcn_mma_kernel(const float* __restrict__ x, const float* __restrict__ cs,
                float* __restrict__ out, int E, int ntiles) {
    extern __shared__ float sm[];
    float* Bph = sm + OFF_BPH;
    float* Bpl = sm + OFF_BPL;
    float* Ah = sm + OFF_AH;
    float* Al = sm + OFF_AL;
    __shared__ float s_xsum[TILE_M];

    const int t = threadIdx.x, wid = t >> 5, lane = t & 31;
    const int g = lane >> 2, tig = lane & 3;
    const int h = wid >> 3;          // N-half
    const int wr = (wid & 7) * 16;   // warp row base
    const int r0 = wr + g;

    // ---- Build permuted B hi/lo from W partials (once per CTA) ----
    for (int idx = t; idx < R_DIM * O_DIM; idx += NTHREADS) {
        const int r = idx >> 8, o = idx & 255;
        float v = 0.0f;
#pragma unroll
        for (int c = 0; c < 8; ++c) v += g_wpart[c][idx];
        float hf = __uint_as_float(cvt_tf32(v));
        const int Q = o >> 6, oq = o & 63;
        const int pos = (Q * 64 + r) * BROW + (oq & 7) * 8 + (oq >> 3);
        Bph[pos] = hf;
        Bpl[pos] = __uint_as_float(cvt_tf32(v - hf));
    }
    __syncthreads();

    for (int tile = blockIdx.x; tile < ntiles; tile += gridDim.x) {
        const int ebase = tile * TILE_M;

        // ---- Build A hi/lo (rcp of cs, tf32-split) into shared ----
        {
            const int el0 = t >> 6, k = t & 63;
#pragma unroll 4
            for (int q = 0; q < 16; ++q) {
                const int el = el0 + q * 8;
                const int e = ebase + el;
                float v = 0.0f;
                if (e < E) v = frcp(cs[(size_t)e * R_DIM + k]);
                float hf = __uint_as_float(cvt_tf32(v));
                Ah[el * ASTR + k] = hf;
                Al[el * ASTR + k] = __uint_as_float(cvt_tf32(v - hf));
            }
        }
        __syncthreads();

        // ---- Load A-hi fragments into registers (32 regs) ----
        // a0=(g,c) a1=(g+8,c) a2=(g,c+4) a3=(g+8,c+4), c = ks*8+tig
        uint32_t ah[8][4];
#pragma unroll
        for (int ks = 0; ks < 8; ++ks) {
            const int c0 = ks * 8 + tig;
            ah[ks][0] = __float_as_uint(Ah[r0 * ASTR + c0]);
            ah[ks][1] = __float_as_uint(Ah[(r0 + 8) * ASTR + c0]);
            ah[ks][2] = __float_as_uint(Ah[r0 * ASTR + c0 + 4]);
            ah[ks][3] = __float_as_uint(Ah[(r0 + 8) * ASTR + c0 + 4]);
        }

        // ---- x row sums: warp wid owns rows wid*8 .. wid*8+7 ----
#pragma unroll 1
        for (int rr = 0; rr < 8; ++rr) {
            const int row = wid * 8 + rr;
            const int e = ebase + row;
            float s = 0.0f;
            if (e < E) {
                const float4* xp = (const float4*)(x + (size_t)e * I_DIM);
                float4 a = xp[lane], b = xp[lane + 32];
                s = ((a.x + a.y) + (a.z + a.w)) + ((b.x + b.y) + (b.z + b.w));
            }
#pragma unroll
            for (int off = 16; off; off >>= 1)
                s += __shfl_xor_sync(0xffffffffu, s, off);
            if (lane == 0) s_xsum[row] = s;
        }
        __syncthreads();
        const float xs0 = s_xsum[r0];
        const float xs1 = s_xsum[r0 + 8];
        const int e0 = ebase + r0, e1 = e0 + 8;

        // ---- Two 64-col quarters of this warp's N-half ----
#pragma unroll
        for (int q = 0; q < 2; ++q) {
            const int Q = h * 2 + q;
            const float* bh_base = Bph + (Q * 64) * BROW + g * 8;
            const float* bl_base = Bpl + (Q * 64) * BROW + g * 8;

            float acc[8][4];
#pragma unroll
            for (int nt = 0; nt < 8; ++nt) {
                acc[nt][0] = 0.f; acc[nt][1] = 0.f;
                acc[nt][2] = 0.f; acc[nt][3] = 0.f;
            }
#pragma unroll
            for (int ks = 0; ks < 8; ++ks) {
                const int row0 = ks * 8 + tig, row1 = row0 + 4;
                // 8 vectorized B-frag loads (two LDS.128 per array per row)
                float4 H0a = *(const float4*)(bh_base + row0 * BROW);
                float4 H0b = *(const float4*)(bh_base + row0 * BROW + 4);
                float4 H1a = *(const float4*)(bh_base + row1 * BROW);
                float4 H1b = *(const float4*)(bh_base + row1 * BROW + 4);
                float4 L0a = *(const float4*)(bl_base + row0 * BROW);
                float4 L0b = *(const float4*)(bl_base + row0 * BROW + 4);
                float4 L1a = *(const float4*)(bl_base + row1 * BROW);
                float4 L1b = *(const float4*)(bl_base + row1 * BROW + 4);
                // A-lo fragment for this ks (transient, from smem)
                uint32_t al[4];
                {
                    const int c0 = ks * 8 + tig;
                    al[0] = __float_as_uint(Al[r0 * ASTR + c0]);
                    al[1] = __float_as_uint(Al[(r0 + 8) * ASTR + c0]);
                    al[2] = __float_as_uint(Al[r0 * ASTR + c0 + 4]);
                    al[3] = __float_as_uint(Al[(r0 + 8) * ASTR + c0 + 4]);
                }
                const float bh0v[8] = {H0a.x, H0a.y, H0a.z, H0a.w,
                                       H0b.x, H0b.y, H0b.z, H0b.w};
                const float bh1v[8] = {H1a.x, H1a.y, H1a.z, H1a.w,
                                       H1b.x, H1b.y, H1b.z, H1b.w};
                const float bl0v[8] = {L0a.x, L0a.y, L0a.z, L0a.w,
                                       L0b.x, L0b.y, L0b.z, L0b.w};
                const float bl1v[8] = {L1a.x, L1a.y, L1a.z, L1a.w,
                                       L1b.x, L1b.y, L1b.z, L1b.w};
#pragma unroll
                for (int nt = 0; nt < 8; ++nt) {
                    const uint32_t bh0 = __float_as_uint(bh0v[nt]);
                    const uint32_t bh1 = __float_as_uint(bh1v[nt]);
                    const uint32_t bl0 = __float_as_uint(bl0v[nt]);
                    const uint32_t bl1 = __float_as_uint(bl1v[nt]);
                    mma8(acc[nt], ah[ks], bh0, bh1);
                    mma8(acc[nt], al, bh0, bh1);
                    mma8(acc[nt], ah[ks], bl0, bl1);
                }
            }
            // store: c0/c1 -> row r0, c2/c3 -> row r0+8; cols 2*tig,2*tig+1
            const int colb = h * 128 + q * 64 + 2 * tig;
#pragma unroll
            for (int nt = 0; nt < 8; ++nt) {
                const int col = colb + nt * 8;
                if (e0 < E) {
                    float2 v = make_float2(acc[nt][0] * xs0, acc[nt][1] * xs0);
                    *(float2*)&out[(size_t)e0 * O_DIM + col] = v;
                }
                if (e1 < E) {
                    float2 v = make_float2(acc[nt][2] * xs1, acc[nt][3] * xs1);
                    *(float2*)&out[(size_t)e1 * O_DIM + col] = v;
                }
            }
        }
        __syncthreads();  // A/xsum consumed before next tile overwrites
    }
}

// ---------------------------------------------------------------------------
// Launch. Inputs (metadata order): x (E*I f32), cs (E*R f32), W (R*I*O f32),
// edge_index (dead). Output: (E, O) f32.
// ---------------------------------------------------------------------------
extern "C" void kernel_launch(void* const* d_in, const int* in_sizes, int n_in,
                              void* d_out, int out_size) {
    const float* x  = (const float*)d_in[0];
    const float* cs = (const float*)d_in[1];
    const float* W  = (const float*)d_in[2];
    float* out = (float*)d_out;

    const int E = in_sizes[1] / R_DIM;
    const int ntiles = (E + TILE_M - 1) / TILE_M;

    dim3 wgrid(R_DIM, 8);
    wsum_part_kernel<<<wgrid, O_DIM>>>(W);

    cudaFuncSetAttribute(rgcn_mma_kernel,
                         cudaFuncAttributeMaxDynamicSharedMemorySize, SMEM_DYN);
    int grid = 148;
    if (grid > ntiles) grid = ntiles;
    rgcn_mma_kernel<<<grid, NTHREADS, SMEM_DYN>>>(x, cs, out, E, ntiles);
}

// round 14
// speedup vs baseline: 1.4022x; 1.1680x over previous
#include <cuda_runtime.h>
#include <cstddef>
#include <cstdint>

#define R_DIM 64
#define I_DIM 256
#define O_DIM 256
#define TILE_M 128
#define BROW 68  // B row stride in floats (64 data + 4 pad)

// Scratch
__device__ float g_wpart[8][R_DIM * O_DIM];
__device__ float g_wsum[R_DIM * O_DIM];

// ---------------------------------------------------------------------------
// W partials + reduce: g_wsum[r][o] = sum_i W[r][i][o]
// ---------------------------------------------------------------------------
__global__ void wsum_part_kernel(const float* __restrict__ W) {
    const int r = blockIdx.x, chunk = blockIdx.y, o = threadIdx.x;
    const float* p = W + ((size_t)r * I_DIM + chunk * 32) * O_DIM + o;
    float s = 0.0f;
#pragma unroll
    for (int i = 0; i < 32; ++i) s += p[(size_t)i * O_DIM];
    g_wpart[chunk][r * O_DIM + o] = s;
}
__global__ void wsum_reduce_kernel() {
    const int idx = blockIdx.x * 256 + threadIdx.x;
    float s = 0.0f;
#pragma unroll
    for (int c = 0; c < 8; ++c) s += g_wpart[c][idx];
    g_wsum[idx] = s;
}

// ---------------------------------------------------------------------------
// Helpers
// ---------------------------------------------------------------------------
__device__ __forceinline__ uint32_t cvt_tf32(float v) {
    uint32_t r;
    asm("cvt.rna.tf32.f32 %0, %1;" : "=r"(r) : "f"(v));
    return r;
}
__device__ __forceinline__ float frcp(float v) {
    float r; asm("rcp.approx.f32 %0, %1;" : "=f"(r) : "f"(v)); return r;
}
__device__ __forceinline__ void mma8(float* d, const uint32_t* a,
                                     uint32_t b0, uint32_t b1) {
    asm volatile(
        "mma.sync.aligned.m16n8k8.row.col.f32.tf32.tf32.f32 "
        "{%0,%1,%2,%3},{%4,%5,%6,%7},{%8,%9},{%0,%1,%2,%3};"
        : "+f"(d[0]), "+f"(d[1]), "+f"(d[2]), "+f"(d[3])
        : "r"(a[0]), "r"(a[1]), "r"(a[2]), "r"(a[3]), "r"(b0), "r"(b1));
}

// Dynamic smem: Bph[2*64*BROW] then Bpl[2*64*BROW] (this CTA's 128-col half,
// fragment-permuted: Bp[Q][k][ (o&7)*8 + (o>>3) ]). 69,632 B -> 3 CTAs/SM.
#define SMEM_DYN (2 * 2 * 64 * BROW * 4)

// ---------------------------------------------------------------------------
// Main: out[e][o] = x_sum[e] * sum_r (1/cs[e][r]) * Wsum[r][o]
// mma.sync tf32, 2-product split (A tf32-rounded, B exactly hi+lo split).
// CTA owns one 128-col half; warp w owns rows 16w..16w+15 of each tile.
// No block barriers inside the tile loop.
// ---------------------------------------------------------------------------
__global__ void __launch_bounds__(256, 3)
rgcn_mma_kernel(const float* __restrict__ x, const float* __restrict__ cs,
                float* __restrict__ out, int E, int ntiles) {
    extern __shared__ float sm[];
    float* Bph = sm;
    float* Bpl = sm + 2 * 64 * BROW;

    const int t = threadIdx.x, wid = t >> 5, lane = t & 31;
    const int g = lane >> 2, tig = lane & 3;
    const int h = blockIdx.x & 1;     // which 128-col half
    const int wr = wid * 16;          // warp row base within tile

    // ---- Stage B hi/lo (fragment-permuted) for this half ----
    for (int idx = t; idx < 64 * 128; idx += 256) {
        const int r = idx >> 7, oc = idx & 127;
        float v = g_wsum[r * O_DIM + h * 128 + oc];
        float hf = __uint_as_float(cvt_tf32(v));
        const int Q = oc >> 6, oq = oc & 63;
        const int pos = (Q * 64 + r) * BROW + (oq & 7) * 8 + (oq >> 3);
        Bph[pos] = hf;
        Bpl[pos] = __uint_as_float(cvt_tf32(v - hf));
    }
    __syncthreads();

    const int tstride = gridDim.x >> 1;
    for (int tile = blockIdx.x >> 1; tile < ntiles; tile += tstride) {
        const int ebase = tile * TILE_M;
        const int r0 = wr + g;
        const int e0 = ebase + r0, e1 = e0 + 8;
        const bool v0 = e0 < E, v1 = e1 < E;

        // ---- A fragments direct from gmem (rcp + tf32 round in regs) ----
        // a0=(row g,c) a1=(row g+8,c) a2=(row g,c+4) a3=(row g+8,c+4)
        uint32_t ah[8][4];
        {
            const float* c0p = cs + (size_t)e0 * R_DIM;
            const float* c1p = cs + (size_t)e1 * R_DIM;
#pragma unroll
            for (int ks = 0; ks < 8; ++ks) {
                const int c0 = ks * 8 + tig;
                float a0 = v0 ? c0p[c0] : 1.0f;
                float a1 = v1 ? c1p[c0] : 1.0f;
                float a2 = v0 ? c0p[c0 + 4] : 1.0f;
                float a3 = v1 ? c1p[c0 + 4] : 1.0f;
                ah[ks][0] = cvt_tf32(frcp(a0));
                ah[ks][1] = cvt_tf32(frcp(a1));
                ah[ks][2] = cvt_tf32(frcp(a2));
                ah[ks][3] = cvt_tf32(frcp(a3));
            }
        }

        // ---- x row sums, barrier-free (every lane keeps its two rows) ----
        float xs0 = 0.0f, xs1 = 0.0f;
#pragma unroll 1
        for (int rr = 0; rr < 16; ++rr) {
            const int e = ebase + wr + rr;
            float s = 0.0f;
            if (e < E) {
                const float4* xp = (const float4*)(x + (size_t)e * I_DIM);
                float4 a = xp[lane], b = xp[lane + 32];
                s = ((a.x + a.y) + (a.z + a.w)) + ((b.x + b.y) + (b.z + b.w));
            }
#pragma unroll
            for (int off = 16; off; off >>= 1)
                s += __shfl_xor_sync(0xffffffffu, s, off);
            if (rr == g) xs0 = s;
            if (rr == g + 8) xs1 = s;
        }

        // ---- Two 64-col quarters: MMAs + direct store ----
#pragma unroll
        for (int q = 0; q < 2; ++q) {
            float acc[8][4];
#pragma unroll
            for (int nt = 0; nt < 8; ++nt) {
                acc[nt][0] = 0.f; acc[nt][1] = 0.f;
                acc[nt][2] = 0.f; acc[nt][3] = 0.f;
            }
#pragma unroll
            for (int ks = 0; ks < 8; ++ks) {
                const int row0 = (q * 64 + ks * 8 + tig) * BROW + g * 8;
                const int row1 = row0 + 4 * BROW;
#pragma unroll
                for (int b2 = 0; b2 < 2; ++b2) {
                    float4 H0 = *(const float4*)(Bph + row0 + b2 * 4);
                    float4 H1 = *(const float4*)(Bph + row1 + b2 * 4);
                    float4 L0 = *(const float4*)(Bpl + row0 + b2 * 4);
                    float4 L1 = *(const float4*)(Bpl + row1 + b2 * 4);
                    const int n0 = b2 * 4;
                    mma8(acc[n0 + 0], ah[ks], __float_as_uint(H0.x), __float_as_uint(H1.x));
                    mma8(acc[n0 + 0], ah[ks], __float_as_uint(L0.x), __float_as_uint(L1.x));
                    mma8(acc[n0 + 1], ah[ks], __float_as_uint(H0.y), __float_as_uint(H1.y));
                    mma8(acc[n0 + 1], ah[ks], __float_as_uint(L0.y), __float_as_uint(L1.y));
                    mma8(acc[n0 + 2], ah[ks], __float_as_uint(H0.z), __float_as_uint(H1.z));
                    mma8(acc[n0 + 2], ah[ks], __float_as_uint(L0.z), __float_as_uint(L1.z));
                    mma8(acc[n0 + 3], ah[ks], __float_as_uint(H0.w), __float_as_uint(H1.w));
                    mma8(acc[n0 + 3], ah[ks], __float_as_uint(L0.w), __float_as_uint(L1.w));
                }
            }
            // store: c0/c1 -> row e0, c2/c3 -> row e1; cols 2*tig, 2*tig+1
            const int colb = h * 128 + q * 64 + 2 * tig;
#pragma unroll
            for (int nt = 0; nt < 8; ++nt) {
                const int col = colb + nt * 8;
                if (v0) {
                    float2 o2 = make_float2(acc[nt][0] * xs0, acc[nt][1] * xs0);
                    *(float2*)&out[(size_t)e0 * O_DIM + col] = o2;
                }
                if (v1) {
                    float2 o2 = make_float2(acc[nt][2] * xs1, acc[nt][3] * xs1);
                    *(float2*)&out[(size_t)e1 * O_DIM + col] = o2;
                }
            }
        }
    }
}

// ---------------------------------------------------------------------------
// Launch. Inputs (metadata order): x (E*I f32), cs (E*R f32), W (R*I*O f32),
// edge_index (dead). Output: (E, O) f32.
// ---------------------------------------------------------------------------
extern "C" void kernel_launch(void* const* d_in, const int* in_sizes, int n_in,
                              void* d_out, int out_size) {
    const float* x  = (const float*)d_in[0];
    const float* cs = (const float*)d_in[1];
    const float* W  = (const float*)d_in[2];
    float* out = (float*)d_out;

    const int E = in_sizes[1] / R_DIM;
    const int ntiles = (E + TILE_M - 1) / TILE_M;

    dim3 wgrid(R_DIM, 8);
    wsum_part_kernel<<<wgrid, O_DIM>>>(W);
    wsum_reduce_kernel<<<R_DIM, 256>>>();

    cudaFuncSetAttribute(rgcn_mma_kernel,
                         cudaFuncAttributeMaxDynamicSharedMemorySize, SMEM_DYN);
    int grid = 444;  // 3 CTAs/SM x 148 SMs; even halves split
    if (grid > 2 * ntiles) grid = 2 * ntiles;
    rgcn_mma_kernel<<<grid, 256, SMEM_DYN>>>(x, cs, out, E, ntiles);
}

// round 16
// speedup vs baseline: 1.4937x; 1.0653x over previous
#include <cuda_runtime.h>
#include <cstddef>
#include <cstdint>

#define R_DIM 64
#define I_DIM 256
#define O_DIM 256
#define TILE_M 128
#define BROW 68  // B row stride in floats (64 data + 4 pad)

// Scratch
__device__ float g_wpart[8][R_DIM * O_DIM];
__device__ float g_wsum[R_DIM * O_DIM];
__device__ float g_xsum[131072];

// ---------------------------------------------------------------------------
// W partials: g_wpart[chunk][r][o] = sum_{i in chunk} W[r][i][o]
// ---------------------------------------------------------------------------
__global__ void wsum_part_kernel(const float* __restrict__ W) {
    const int r = blockIdx.x, chunk = blockIdx.y, o = threadIdx.x;
    const float* p = W + ((size_t)r * I_DIM + chunk * 32) * O_DIM + o;
    float s = 0.0f;
#pragma unroll
    for (int i = 0; i < 32; ++i) s += p[(size_t)i * O_DIM];
    g_wpart[chunk][r * O_DIM + o] = s;
}

__global__ void wsum_reduce_kernel() {
    const int idx = blockIdx.x * 256 + threadIdx.x;
    float s = 0.0f;
#pragma unroll
    for (int c = 0; c < 8; ++c) s += g_wpart[c][idx];
    g_wsum[idx] = s;
}

// ---------------------------------------------------------------------------
// x row sums: one warp per row, 8 rows per 256-thread CTA.
// ---------------------------------------------------------------------------
__global__ void xsum_kernel(const float* __restrict__ x, int E) {
    const int wid = threadIdx.x >> 5, lane = threadIdx.x & 31;
    const int row = blockIdx.x * 8 + wid;
    if (row < E) {
        const float4* p = (const float4*)(x + (size_t)row * I_DIM);
        float4 a = p[lane], b = p[lane + 32];
        float s = ((a.x + a.y) + (a.z + a.w)) + ((b.x + b.y) + (b.z + b.w));
#pragma unroll
        for (int off = 16; off; off >>= 1)
            s += __shfl_xor_sync(0xffffffffu, s, off);
        if (lane == 0) g_xsum[row] = s;
    }
}

// ---------------------------------------------------------------------------
// Helpers
// ---------------------------------------------------------------------------
__device__ __forceinline__ uint32_t cvt_tf32(float v) {
    uint32_t r;
    asm("cvt.rna.tf32.f32 %0, %1;" : "=r"(r) : "f"(v));
    return r;
}
__device__ __forceinline__ float frcp(float v) {
    float r; asm("rcp.approx.f32 %0, %1;" : "=f"(r) : "f"(v)); return r;
}
__device__ __forceinline__ void mma8(float* d, const uint32_t* a,
                                     uint32_t b0, uint32_t b1) {
    asm volatile(
        "mma.sync.aligned.m16n8k8.row.col.f32.tf32.tf32.f32 "
        "{%0,%1,%2,%3},{%4,%5,%6,%7},{%8,%9},{%0,%1,%2,%3};"
        : "+f"(d[0]), "+f"(d[1]), "+f"(d[2]), "+f"(d[3])
        : "r"(a[0]), "r"(a[1]), "r"(a[2]), "r"(a[3]), "r"(b0), "r"(b1));
}

// Dynamic smem: Bph then Bpl for this CTA's 128-col half, fragment-permuted
// Bp[Q][k][(o&7)*8 + (o>>3)], row stride BROW. 69,632 B -> 3 CTAs/SM.
#define SMEM_DYN (2 * 2 * 64 * BROW * 4)

// ---------------------------------------------------------------------------
// Main: out[e][o] = x_sum[e] * sum_r (1/cs[e][r]) * Wsum[r][o]
// mma.sync tf32, 2-product split (A tf32-rounded, B exact hi+lo in smem).
// CTA owns one 128-col half; warp w owns rows 16w..16w+15 of each tile.
// No x reads, no shuffles, no block barriers in the tile loop.
// ---------------------------------------------------------------------------
__global__ void __launch_bounds__(256, 3)
rgcn_mma_kernel(const float* __restrict__ cs, float* __restrict__ out,
                int E, int ntiles) {
    extern __shared__ float sm[];
    float* Bph = sm;
    float* Bpl = sm + 2 * 64 * BROW;

    const int t = threadIdx.x, wid = t >> 5, lane = t & 31;
    const int g = lane >> 2, tig = lane & 3;
    const int h = blockIdx.x & 1;  // which 128-col half
    const int wr = wid * 16;       // warp row base within tile

    // ---- Stage B hi/lo (fragment-permuted) for this half ----
    for (int idx = t; idx < 64 * 128; idx += 256) {
        const int r = idx >> 7, oc = idx & 127;
        float v = g_wsum[r * O_DIM + h * 128 + oc];
        float hf = __uint_as_float(cvt_tf32(v));
        const int Q = oc >> 6, oq = oc & 63;
        const int pos = (Q * 64 + r) * BROW + (oq & 7) * 8 + (oq >> 3);
        Bph[pos] = hf;
        Bpl[pos] = __uint_as_float(cvt_tf32(v - hf));
    }
    __syncthreads();

    const int tstride = gridDim.x >> 1;
    for (int tile = blockIdx.x >> 1; tile < ntiles; tile += tstride) {
        const int ebase = tile * TILE_M;
        const int r0 = wr + g;
        const int e0 = ebase + r0, e1 = e0 + 8;
        const bool v0 = e0 < E, v1 = e1 < E;

        // ---- A fragments direct from gmem (rcp + tf32 round in regs) ----
        uint32_t ah[8][4];
        {
            const float* c0p = cs + (size_t)e0 * R_DIM;
            const float* c1p = cs + (size_t)e1 * R_DIM;
#pragma unroll
            for (int ks = 0; ks < 8; ++ks) {
                const int c0 = ks * 8 + tig;
                float a0 = v0 ? c0p[c0] : 1.0f;
                float a1 = v1 ? c1p[c0] : 1.0f;
                float a2 = v0 ? c0p[c0 + 4] : 1.0f;
                float a3 = v1 ? c1p[c0 + 4] : 1.0f;
                ah[ks][0] = cvt_tf32(frcp(a0));
                ah[ks][1] = cvt_tf32(frcp(a1));
                ah[ks][2] = cvt_tf32(frcp(a2));
                ah[ks][3] = cvt_tf32(frcp(a3));
            }
        }

        // ---- Row scales from precomputed x sums ----
        const float xs0 = v0 ? g_xsum[e0] : 0.0f;
        const float xs1 = v1 ? g_xsum[e1] : 0.0f;

        // ---- Two 64-col quarters: MMAs + direct store ----
#pragma unroll
        for (int q = 0; q < 2; ++q) {
            float acc[8][4];
#pragma unroll
            for (int nt = 0; nt < 8; ++nt) {
                acc[nt][0] = 0.f; acc[nt][1] = 0.f;
                acc[nt][2] = 0.f; acc[nt][3] = 0.f;
            }
#pragma unroll
            for (int ks = 0; ks < 8; ++ks) {
                const int row0 = (q * 64 + ks * 8 + tig) * BROW + g * 8;
                const int row1 = row0 + 4 * BROW;
#pragma unroll
                for (int b2 = 0; b2 < 2; ++b2) {
                    float4 H0 = *(const float4*)(Bph + row0 + b2 * 4);
                    float4 H1 = *(const float4*)(Bph + row1 + b2 * 4);
                    float4 L0 = *(const float4*)(Bpl + row0 + b2 * 4);
                    float4 L1 = *(const float4*)(Bpl + row1 + b2 * 4);
                    const int n0 = b2 * 4;
                    mma8(acc[n0 + 0], ah[ks], __float_as_uint(H0.x), __float_as_uint(H1.x));
                    mma8(acc[n0 + 0], ah[ks], __float_as_uint(L0.x), __float_as_uint(L1.x));
                    mma8(acc[n0 + 1], ah[ks], __float_as_uint(H0.y), __float_as_uint(H1.y));
                    mma8(acc[n0 + 1], ah[ks], __float_as_uint(L0.y), __float_as_uint(L1.y));
                    mma8(acc[n0 + 2], ah[ks], __float_as_uint(H0.z), __float_as_uint(H1.z));
                    mma8(acc[n0 + 2], ah[ks], __float_as_uint(L0.z), __float_as_uint(L1.z));
                    mma8(acc[n0 + 3], ah[ks], __float_as_uint(H0.w), __float_as_uint(H1.w));
                    mma8(acc[n0 + 3], ah[ks], __float_as_uint(L0.w), __float_as_uint(L1.w));
                }
            }
            // store: c0/c1 -> row e0, c2/c3 -> row e1; cols 2*tig, 2*tig+1
            const int colb = h * 128 + q * 64 + 2 * tig;
#pragma unroll
            for (int nt = 0; nt < 8; ++nt) {
                const int col = colb + nt * 8;
                if (v0) {
                    float2 o2 = make_float2(acc[nt][0] * xs0, acc[nt][1] * xs0);
                    *(float2*)&out[(size_t)e0 * O_DIM + col] = o2;
                }
                if (v1) {
                    float2 o2 = make_float2(acc[nt][2] * xs1, acc[nt][3] * xs1);
                    *(float2*)&out[(size_t)e1 * O_DIM + col] = o2;
                }
            }
        }
    }
}

// ---------------------------------------------------------------------------
// Launch. Inputs (metadata order): x (E*I f32), cs (E*R f32), W (R*I*O f32),
// edge_index (dead). Output: (E, O) f32.
// The two prepass kernels are independent (different inputs/outputs) and can
// overlap; wsum_reduce and the main kernel consume their results in order.
// ---------------------------------------------------------------------------
extern "C" void kernel_launch(void* const* d_in, const int* in_sizes, int n_in,
                              void* d_out, int out_size) {
    const float* x  = (const float*)d_in[0];
    const float* cs = (const float*)d_in[1];
    const float* W  = (const float*)d_in[2];
    float* out = (float*)d_out;

    const int E = in_sizes[1] / R_DIM;
    const int ntiles = (E + TILE_M - 1) / TILE_M;

    dim3 wgrid(R_DIM, 8);
    wsum_part_kernel<<<wgrid, O_DIM>>>(W);
    xsum_kernel<<<(E + 7) / 8, 256>>>(x, E);
    wsum_reduce_kernel<<<R_DIM, 256>>>();

    cudaFuncSetAttribute(rgcn_mma_kernel,
                         cudaFuncAttributeMaxDynamicSharedMemorySize, SMEM_DYN);
    int grid = 444;  // 3 CTAs/SM x 148 SMs; even/odd = column halves
    if (grid > 2 * ntiles) grid = 2 * ntiles;
    rgcn_mma_kernel<<<grid, 256, SMEM_DYN>>>(cs, out, E, ntiles);
}